// round 9
// baseline (speedup 1.0000x reference)
#include <cuda_runtime.h>

#define BB 8
#define CC 4
#define HH 512
#define WW 512
#define RPW 16                         // rows per warp strip
#define NSTRIPS (HH / RPW)             // 32
#define NPLANE (BB * CC)               // 32
#define NT 256
#define WPB (NT / 32)                  // 8 warps/block
#define NBLK (NPLANE * NSTRIPS * 4 / WPB)   // 512

__device__ float4 g_part[NBLK];
__device__ int g_ctr = 0;

__device__ __forceinline__ float sigm(float x) {
    float t;
    asm("tanh.approx.f32 %0, %1;" : "=f"(t) : "f"(0.5f * x));
    return __fmaf_rn(0.5f, t, 0.5f);
}
__device__ __forceinline__ unsigned prmt(unsigned a, unsigned b, unsigned s) {
    unsigned r;
    asm("prmt.b32 %0, %1, %2, %3;" : "=r"(r) : "r"(a), "r"(b), "r"(s));
    return r;
}
__device__ __forceinline__ float fand(float v, unsigned m) {
    return __uint_as_float(__float_as_uint(v) & m);
}

struct Row {
    float s0, s1, s2, s3, d0, d1, d2, d3;   // horizontal sobel partials (probs)
    unsigned sb, db;                        // packed-byte partials (targets)
};

// Unguarded fetch: row gr MUST be in [0, HH). No branches around the main loads.
template <bool DICE>
__device__ __forceinline__ Row fetch(const float* __restrict__ lg,
                                     const float* __restrict__ tg,
                                     int gr, int c0, int lane,
                                     bool lEdge, bool rEdge,
                                     float& s_pt, float& s_p, int& s_ti)
{
    const float* rowp = lg + (size_t)gr * WW + c0;
    const float* rowt = tg + (size_t)gr * WW + c0;
    float4 x  = __ldg((const float4*)rowp);
    float4 tv = __ldg((const float4*)rowt);

    float xl = 0.f, xr = 0.f;
    unsigned tl = 0u, tr = 0u;
    if (lane == 0 && lEdge) {
        xl = __ldg(rowp - 1);
        tl = __float_as_uint(__ldg(rowt - 1)) >> 29;
    }
    if (lane == 31 && rEdge) {
        xr = __ldg(rowp + 4);
        tr = __float_as_uint(__ldg(rowt + 4)) >> 29;
    }

    float4 pv;
    pv.x = sigm(x.x); pv.y = sigm(x.y); pv.z = sigm(x.z); pv.w = sigm(x.w);
    unsigned q1 = prmt(__float_as_uint(tv.x), __float_as_uint(tv.y), 0x0073u);
    unsigned q2 = prmt(__float_as_uint(tv.z), __float_as_uint(tv.w), 0x7300u);
    unsigned tw = (q1 | q2) & 0x01010101u;

    if (DICE) {
        s_pt = __fmaf_rn(pv.x, tv.x, s_pt);
        s_pt = __fmaf_rn(pv.y, tv.y, s_pt);
        s_pt = __fmaf_rn(pv.z, tv.z, s_pt);
        s_pt = __fmaf_rn(pv.w, tv.w, s_pt);
        s_p += (pv.x + pv.y) + (pv.z + pv.w);
        s_ti += __popc(tw);
    }

    float plin = __shfl_up_sync(0xffffffffu, pv.w, 1);
    float prin = __shfl_down_sync(0xffffffffu, pv.x, 1);
    unsigned twl = __shfl_up_sync(0xffffffffu, tw, 1);
    unsigned twr = __shfl_down_sync(0xffffffffu, tw, 1);
    float pl = plin, pr = prin;
    unsigned tli = twl >> 24, tri = twr & 0xffu;
    if (lane == 0)  { pl = lEdge ? sigm(xl) : 0.f; tli = tl; }
    if (lane == 31) { pr = rEdge ? sigm(xr) : 0.f; tri = tr; }

    Row h;
    h.s0 = __fmaf_rn(2.f, pv.x, pl   + pv.y); h.d0 = pv.y - pl;
    h.s1 = __fmaf_rn(2.f, pv.y, pv.x + pv.z); h.d1 = pv.z - pv.x;
    h.s2 = __fmaf_rn(2.f, pv.z, pv.y + pv.w); h.d2 = pv.w - pv.y;
    h.s3 = __fmaf_rn(2.f, pv.w, pv.z + pr);   h.d3 = pr   - pv.z;
    unsigned wl = (tw << 8) | tli;
    unsigned wr = (tw >> 8) | (tri << 24);
    h.sb = wl + 2u * tw + wr;
    h.db = (wr + 0x02020202u) - wl;
    return h;
}

// Halo fetch: row may be out of range; load from clamped row, mask results.
__device__ __forceinline__ Row fetch_halo(const float* __restrict__ lg,
                                          const float* __restrict__ tg,
                                          int gr, int c0, int lane,
                                          bool lEdge, bool rEdge)
{
    const unsigned msk = ((unsigned)gr < (unsigned)HH) ? 0xffffffffu : 0u;
    int grc = gr < 0 ? 0 : (gr >= HH ? HH - 1 : gr);
    float dpt = 0.f, dp = 0.f; int dti = 0;   // dummies (no dice on halo)
    Row h = fetch<false>(lg, tg, grc, c0, lane, lEdge, rEdge, dpt, dp, dti);
    h.s0 = fand(h.s0, msk); h.s1 = fand(h.s1, msk);
    h.s2 = fand(h.s2, msk); h.s3 = fand(h.s3, msk);
    h.d0 = fand(h.d0, msk); h.d1 = fand(h.d1, msk);
    h.d2 = fand(h.d2, msk); h.d3 = fand(h.d3, msk);
    h.sb &= msk;
    h.db = (h.db & msk) | (0x02020202u & ~msk);   // biased zero when invalid
    return h;
}

__device__ __forceinline__ int combine(const Row& h0, const Row& h1, const Row& h2)
{
    float gx0 = __fmaf_rn(2.f, h1.d0, h0.d0 + h2.d0);
    float gx1 = __fmaf_rn(2.f, h1.d1, h0.d1 + h2.d1);
    float gx2 = __fmaf_rn(2.f, h1.d2, h0.d2 + h2.d2);
    float gx3 = __fmaf_rn(2.f, h1.d3, h0.d3 + h2.d3);
    float gy0 = h2.s0 - h0.s0;
    float gy1 = h2.s1 - h0.s1;
    float gy2 = h2.s2 - h0.s2;
    float gy3 = h2.s3 - h0.s3;
    bool pb0 = __fmaf_rn(gx0, gx0, gy0 * gy0) > 0.25f;
    bool pb1 = __fmaf_rn(gx1, gx1, gy1 * gy1) > 0.25f;
    bool pb2 = __fmaf_rn(gx2, gx2, gy2 * gy2) > 0.25f;
    bool pb3 = __fmaf_rn(gx3, gx3, gy3 * gy3) > 0.25f;

    unsigned hx = h0.db + 2u * h1.db + h2.db;     // ==8 per lane <=> hx_true==0
    unsigned hy = (h2.sb + 0x04040404u) - h0.sb;  // ==4 per lane <=> hy_true==0
    unsigned cmb = (hx ^ 0x08080808u) | (hy ^ 0x04040404u);

    int m = 0;
    m += (int)(pb0 != ((cmb & 0x000000FFu) != 0));
    m += (int)(pb1 != ((cmb & 0x0000FF00u) != 0));
    m += (int)(pb2 != ((cmb & 0x00FF0000u) != 0));
    m += (int)(pb3 != ((cmb >> 24) != 0));
    return m;
}

__global__ __launch_bounds__(NT, 4) void loss_fused(
    const float* __restrict__ logits, const float* __restrict__ targets,
    const float* __restrict__ cw, float* __restrict__ out)
{
    __shared__ float red[WPB][4];
    __shared__ float s_dice[NPLANE];
    __shared__ float s_mm[NPLANE];
    __shared__ int s_isLast;

    const int lane = threadIdx.x & 31;
    const int gw = blockIdx.x * WPB + (threadIdx.x >> 5);
    const int cg    = gw & 3;                    // column group 0..3
    const int strip = (gw >> 2) & (NSTRIPS - 1); // 0..31
    const int plane = gw >> 7;                   // 0..31
    const int c0 = cg * 128 + lane * 4;
    const bool lEdge = (cg > 0);
    const bool rEdge = (cg < 3);
    const int row0 = strip * RPW;

    const float* lg = logits  + (size_t)plane * HH * WW;
    const float* tg = targets + (size_t)plane * HH * WW;

    float s_pt = 0.f, s_p = 0.f;
    int s_ti = 0, s_mi = 0;

    // prologue: top halo (masked) + first interior row
    Row h0 = fetch_halo(lg, tg, row0 - 1, c0, lane, lEdge, rEdge);
    Row h1 = fetch<true>(lg, tg, row0, c0, lane, lEdge, rEdge, s_pt, s_p, s_ti);

    // hot loop: rows row0+1 .. row0+RPW-1 are always in range — branch-free
    #pragma unroll
    for (int k = 0; k < RPW - 1; k++) {
        Row h2 = fetch<true>(lg, tg, row0 + k + 1, c0, lane, lEdge, rEdge,
                             s_pt, s_p, s_ti);
        s_mi += combine(h0, h1, h2);
        h0 = h1; h1 = h2;
    }
    // epilogue: bottom halo (masked)
    {
        Row h2 = fetch_halo(lg, tg, row0 + RPW, c0, lane, lEdge, rEdge);
        s_mi += combine(h0, h1, h2);
    }

    // ---- warp reduce ----
    float s_t = (float)s_ti, s_m = (float)s_mi;
    #pragma unroll
    for (int o = 16; o > 0; o >>= 1) {
        s_pt += __shfl_down_sync(0xffffffffu, s_pt, o);
        s_p  += __shfl_down_sync(0xffffffffu, s_p,  o);
        s_t  += __shfl_down_sync(0xffffffffu, s_t,  o);
        s_m  += __shfl_down_sync(0xffffffffu, s_m,  o);
    }
    int w = threadIdx.x >> 5;
    if (lane == 0) {
        red[w][0] = s_pt; red[w][1] = s_p; red[w][2] = s_t; red[w][3] = s_m;
    }
    __syncthreads();
    if (threadIdx.x == 0) {
        float a = 0.f, b = 0.f, c2 = 0.f, d = 0.f;
        #pragma unroll
        for (int j = 0; j < WPB; j++) {
            a += red[j][0]; b += red[j][1]; c2 += red[j][2]; d += red[j][3];
        }
        g_part[blockIdx.x] = make_float4(a, b, c2, d);
        __threadfence();
        int v = atomicAdd(&g_ctr, 1);
        s_isLast = (v == NBLK - 1);
    }
    __syncthreads();

    // ---- final reduction in last block ----
    if (s_isLast) {
        __threadfence();
        int tid = threadIdx.x;
        if (tid < NPLANE) {
            float a = 0.f, b = 0.f, c2 = 0.f, m = 0.f;
            #pragma unroll 4
            for (int s = 0; s < NBLK / NPLANE; s++) {
                float4 v = g_part[tid * (NBLK / NPLANE) + s];
                a += v.x; b += v.y; c2 += v.z; m += v.w;
            }
            s_dice[tid] = (2.0f * a + 1.0f) / (b + c2 + 1.0f);  // SMOOTH=1
            s_mm[tid] = m;
        }
        __syncthreads();
        if (tid == 0) {
            float mt = 0.0f;
            #pragma unroll
            for (int j = 0; j < NPLANE; j++) mt += s_mm[j];

            float wsum = 0.0f, dl = 0.0f;
            #pragma unroll
            for (int c = 0; c < CC; c++) {
                float acc = 0.0f;
                #pragma unroll
                for (int b = 0; b < BB; b++) acc += s_dice[b * CC + c];
                dl += cw[c] * (1.0f - acc / (float)BB);
                wsum += cw[c];
            }
            dl /= wsum;
            float bl = 100.0f * mt / (float)((long long)BB * CC * HH * WW);
            out[0] = 0.7f * dl + 0.3f * bl;
            g_ctr = 0;   // reset for next graph replay
        }
    }
}

extern "C" void kernel_launch(void* const* d_in, const int* in_sizes, int n_in,
                              void* d_out, int out_size)
{
    const float* logits  = (const float*)d_in[0];
    const float* targets = (const float*)d_in[1];
    const float* cw      = (const float*)d_in[2];

    loss_fused<<<NBLK, NT>>>(logits, targets, cw, (float*)d_out);
}

// round 10
// speedup vs baseline: 1.1065x; 1.1065x over previous
#include <cuda_runtime.h>

#define BB 8
#define CC 4
#define HH 512
#define WW 512
#define RPW 16                         // rows per warp strip
#define NSTRIPS (HH / RPW)             // 32
#define NPLANE (BB * CC)               // 32
#define NT 256
#define WPB (NT / 32)                  // 8 warps/block
#define NBLK (NPLANE * NSTRIPS * 2 / WPB)   // 256 (2 column groups of 256)

__device__ float4 g_part[NBLK];
__device__ int g_ctr = 0;

__device__ __forceinline__ float sigm(float x) {
    float t;
    asm("tanh.approx.f32 %0, %1;" : "=f"(t) : "f"(0.5f * x));
    return __fmaf_rn(0.5f, t, 0.5f);
}
__device__ __forceinline__ unsigned prmt(unsigned a, unsigned b, unsigned s) {
    unsigned r;
    asm("prmt.b32 %0, %1, %2, %3;" : "=r"(r) : "r"(a), "r"(b), "r"(s));
    return r;
}
__device__ __forceinline__ float fand(float v, unsigned m) {
    return __uint_as_float(__float_as_uint(v) & m);
}

struct Row {
    float s[8], d[8];          // horizontal sobel partials (probs), 8 columns
    unsigned sb0, sb1, db0, db1;  // packed-byte partials (targets)
};

// Unguarded fetch: row gr MUST be in [0, HH).
template <bool DICE>
__device__ __forceinline__ Row fetch(const float* __restrict__ lg,
                                     const float* __restrict__ tg,
                                     int gr, int c0, int lane,
                                     bool lEdge, bool rEdge,
                                     float& s_pt, float& s_p, int& s_ti)
{
    const float* rowp = lg + (size_t)gr * WW + c0;
    const float* rowt = tg + (size_t)gr * WW + c0;
    float4 xa = __ldg((const float4*)rowp);
    float4 xb = __ldg((const float4*)(rowp + 4));
    float4 ta = __ldg((const float4*)rowt);
    float4 tb = __ldg((const float4*)(rowt + 4));

    float xl = 0.f, xr = 0.f;
    unsigned tl = 0u, tr = 0u;
    if (lane == 0 && lEdge) {
        xl = __ldg(rowp - 1);
        tl = __float_as_uint(__ldg(rowt - 1)) >> 29;
    }
    if (lane == 31 && rEdge) {
        xr = __ldg(rowp + 8);
        tr = __float_as_uint(__ldg(rowt + 8)) >> 29;
    }

    float p[8];
    p[0] = sigm(xa.x); p[1] = sigm(xa.y); p[2] = sigm(xa.z); p[3] = sigm(xa.w);
    p[4] = sigm(xb.x); p[5] = sigm(xb.y); p[6] = sigm(xb.z); p[7] = sigm(xb.w);
    unsigned q1 = prmt(__float_as_uint(ta.x), __float_as_uint(ta.y), 0x0073u);
    unsigned q2 = prmt(__float_as_uint(ta.z), __float_as_uint(ta.w), 0x7300u);
    unsigned tw0 = (q1 | q2) & 0x01010101u;
    unsigned q3 = prmt(__float_as_uint(tb.x), __float_as_uint(tb.y), 0x0073u);
    unsigned q4 = prmt(__float_as_uint(tb.z), __float_as_uint(tb.w), 0x7300u);
    unsigned tw1 = (q3 | q4) & 0x01010101u;

    if (DICE) {
        s_pt = __fmaf_rn(p[0], ta.x, s_pt);
        s_pt = __fmaf_rn(p[1], ta.y, s_pt);
        s_pt = __fmaf_rn(p[2], ta.z, s_pt);
        s_pt = __fmaf_rn(p[3], ta.w, s_pt);
        s_pt = __fmaf_rn(p[4], tb.x, s_pt);
        s_pt = __fmaf_rn(p[5], tb.y, s_pt);
        s_pt = __fmaf_rn(p[6], tb.z, s_pt);
        s_pt = __fmaf_rn(p[7], tb.w, s_pt);
        s_p += ((p[0] + p[1]) + (p[2] + p[3])) + ((p[4] + p[5]) + (p[6] + p[7]));
        s_ti += __popc(tw0) + __popc(tw1);
    }

    float plin = __shfl_up_sync(0xffffffffu, p[7], 1);
    float prin = __shfl_down_sync(0xffffffffu, p[0], 1);
    unsigned twl = __shfl_up_sync(0xffffffffu, tw1, 1);
    unsigned twr = __shfl_down_sync(0xffffffffu, tw0, 1);
    float pl = plin, pr = prin;
    unsigned tli = twl >> 24, tri = twr & 0xffu;
    if (lane == 0)  { pl = lEdge ? sigm(xl) : 0.f; tli = tl; }
    if (lane == 31) { pr = rEdge ? sigm(xr) : 0.f; tri = tr; }

    Row h;
    h.s[0] = __fmaf_rn(2.f, p[0], pl   + p[1]); h.d[0] = p[1] - pl;
    #pragma unroll
    for (int i = 1; i < 7; i++) {
        h.s[i] = __fmaf_rn(2.f, p[i], p[i-1] + p[i+1]);
        h.d[i] = p[i+1] - p[i-1];
    }
    h.s[7] = __fmaf_rn(2.f, p[7], p[6] + pr);   h.d[7] = pr - p[6];

    unsigned wl0 = (tw0 << 8) | tli;
    unsigned wr0 = (tw0 >> 8) | ((tw1 & 0xffu) << 24);
    h.sb0 = wl0 + 2u * tw0 + wr0;
    h.db0 = (wr0 + 0x02020202u) - wl0;
    unsigned wl1 = (tw1 << 8) | (tw0 >> 24);
    unsigned wr1 = (tw1 >> 8) | (tri << 24);
    h.sb1 = wl1 + 2u * tw1 + wr1;
    h.db1 = (wr1 + 0x02020202u) - wl1;
    return h;
}

// Halo fetch: row may be out of range; load from clamped row, mask results.
__device__ __forceinline__ Row fetch_halo(const float* __restrict__ lg,
                                          const float* __restrict__ tg,
                                          int gr, int c0, int lane,
                                          bool lEdge, bool rEdge)
{
    const unsigned msk = ((unsigned)gr < (unsigned)HH) ? 0xffffffffu : 0u;
    int grc = gr < 0 ? 0 : (gr >= HH ? HH - 1 : gr);
    float dpt = 0.f, dp = 0.f; int dti = 0;
    Row h = fetch<false>(lg, tg, grc, c0, lane, lEdge, rEdge, dpt, dp, dti);
    #pragma unroll
    for (int i = 0; i < 8; i++) {
        h.s[i] = fand(h.s[i], msk);
        h.d[i] = fand(h.d[i], msk);
    }
    h.sb0 &= msk; h.sb1 &= msk;
    h.db0 = (h.db0 & msk) | (0x02020202u & ~msk);
    h.db1 = (h.db1 & msk) | (0x02020202u & ~msk);
    return h;
}

__device__ __forceinline__ int combine(const Row& h0, const Row& h1, const Row& h2)
{
    bool pb[8];
    #pragma unroll
    for (int i = 0; i < 8; i++) {
        float gx = __fmaf_rn(2.f, h1.d[i], h0.d[i] + h2.d[i]);
        float gy = h2.s[i] - h0.s[i];
        pb[i] = __fmaf_rn(gx, gx, gy * gy) > 0.25f;
    }
    unsigned hx0 = h0.db0 + 2u * h1.db0 + h2.db0;
    unsigned hy0 = (h2.sb0 + 0x04040404u) - h0.sb0;
    unsigned cmb0 = (hx0 ^ 0x08080808u) | (hy0 ^ 0x04040404u);
    unsigned hx1 = h0.db1 + 2u * h1.db1 + h2.db1;
    unsigned hy1 = (h2.sb1 + 0x04040404u) - h0.sb1;
    unsigned cmb1 = (hx1 ^ 0x08080808u) | (hy1 ^ 0x04040404u);

    int m = 0;
    m += (int)(pb[0] != ((cmb0 & 0x000000FFu) != 0));
    m += (int)(pb[1] != ((cmb0 & 0x0000FF00u) != 0));
    m += (int)(pb[2] != ((cmb0 & 0x00FF0000u) != 0));
    m += (int)(pb[3] != ((cmb0 >> 24) != 0));
    m += (int)(pb[4] != ((cmb1 & 0x000000FFu) != 0));
    m += (int)(pb[5] != ((cmb1 & 0x0000FF00u) != 0));
    m += (int)(pb[6] != ((cmb1 & 0x00FF0000u) != 0));
    m += (int)(pb[7] != ((cmb1 >> 24) != 0));
    return m;
}

__global__ __launch_bounds__(NT, 2) void loss_fused(
    const float* __restrict__ logits, const float* __restrict__ targets,
    const float* __restrict__ cw, float* __restrict__ out)
{
    __shared__ float red[WPB][4];
    __shared__ float s_dice[NPLANE];
    __shared__ float s_mm[NPLANE];
    __shared__ int s_isLast;

    const int lane = threadIdx.x & 31;
    const int gw = blockIdx.x * WPB + (threadIdx.x >> 5);
    const int cg    = gw & 1;                    // column group 0..1 (256 cols each)
    const int strip = (gw >> 1) & (NSTRIPS - 1); // 0..31
    const int plane = gw >> 6;                   // 0..31
    const int c0 = cg * 256 + lane * 8;
    const bool lEdge = (cg > 0);
    const bool rEdge = (cg < 1);
    const int row0 = strip * RPW;

    const float* lg = logits  + (size_t)plane * HH * WW;
    const float* tg = targets + (size_t)plane * HH * WW;

    float s_pt = 0.f, s_p = 0.f;
    int s_ti = 0, s_mi = 0;

    // prologue: top halo (masked) + first interior row
    Row h0 = fetch_halo(lg, tg, row0 - 1, c0, lane, lEdge, rEdge);
    Row h1 = fetch<true>(lg, tg, row0, c0, lane, lEdge, rEdge, s_pt, s_p, s_ti);

    // hot loop: rows row0+1 .. row0+RPW-1 always in range — branch-free
    #pragma unroll
    for (int k = 0; k < RPW - 1; k++) {
        Row h2 = fetch<true>(lg, tg, row0 + k + 1, c0, lane, lEdge, rEdge,
                             s_pt, s_p, s_ti);
        s_mi += combine(h0, h1, h2);
        h0 = h1; h1 = h2;
    }
    // epilogue: bottom halo (masked)
    {
        Row h2 = fetch_halo(lg, tg, row0 + RPW, c0, lane, lEdge, rEdge);
        s_mi += combine(h0, h1, h2);
    }

    // ---- warp reduce ----
    float s_t = (float)s_ti, s_m = (float)s_mi;
    #pragma unroll
    for (int o = 16; o > 0; o >>= 1) {
        s_pt += __shfl_down_sync(0xffffffffu, s_pt, o);
        s_p  += __shfl_down_sync(0xffffffffu, s_p,  o);
        s_t  += __shfl_down_sync(0xffffffffu, s_t,  o);
        s_m  += __shfl_down_sync(0xffffffffu, s_m,  o);
    }
    int w = threadIdx.x >> 5;
    if (lane == 0) {
        red[w][0] = s_pt; red[w][1] = s_p; red[w][2] = s_t; red[w][3] = s_m;
    }
    __syncthreads();
    if (threadIdx.x == 0) {
        float a = 0.f, b = 0.f, c2 = 0.f, d = 0.f;
        #pragma unroll
        for (int j = 0; j < WPB; j++) {
            a += red[j][0]; b += red[j][1]; c2 += red[j][2]; d += red[j][3];
        }
        g_part[blockIdx.x] = make_float4(a, b, c2, d);   // plane = blockIdx.x >> 3
        __threadfence();
        int v = atomicAdd(&g_ctr, 1);
        s_isLast = (v == NBLK - 1);
    }
    __syncthreads();

    // ---- final reduction in last block ----
    if (s_isLast) {
        __threadfence();
        int tid = threadIdx.x;
        if (tid < NPLANE) {
            float a = 0.f, b = 0.f, c2 = 0.f, m = 0.f;
            #pragma unroll
            for (int s = 0; s < NBLK / NPLANE; s++) {
                float4 v = g_part[tid * (NBLK / NPLANE) + s];
                a += v.x; b += v.y; c2 += v.z; m += v.w;
            }
            s_dice[tid] = (2.0f * a + 1.0f) / (b + c2 + 1.0f);  // SMOOTH=1
            s_mm[tid] = m;
        }
        __syncthreads();
        if (tid == 0) {
            float mt = 0.0f;
            #pragma unroll
            for (int j = 0; j < NPLANE; j++) mt += s_mm[j];

            float wsum = 0.0f, dl = 0.0f;
            #pragma unroll
            for (int c = 0; c < CC; c++) {
                float acc = 0.0f;
                #pragma unroll
                for (int b = 0; b < BB; b++) acc += s_dice[b * CC + c];
                dl += cw[c] * (1.0f - acc / (float)BB);
                wsum += cw[c];
            }
            dl /= wsum;
            float bl = 100.0f * mt / (float)((long long)BB * CC * HH * WW);
            out[0] = 0.7f * dl + 0.3f * bl;
            g_ctr = 0;   // reset for next graph replay
        }
    }
}

extern "C" void kernel_launch(void* const* d_in, const int* in_sizes, int n_in,
                              void* d_out, int out_size)
{
    const float* logits  = (const float*)d_in[0];
    const float* targets = (const float*)d_in[1];
    const float* cw      = (const float*)d_in[2];

    loss_fused<<<NBLK, NT>>>(logits, targets, cw, (float*)d_out);
}